// round 1
// baseline (speedup 1.0000x reference)
#include <cuda_runtime.h>
#include <math.h>

#define IMG_W 256
#define IMG_H 256
#define GAB   4
#define MAXN  4096
#define SIGMA_T 30.0f

// Scratch (static __device__ globals — no allocation).
// slot 0 = low (gaussian), slot 1 = high (gabor)
__device__ float4 d_geoA[2][MAXN];  // x, y, c0, c1
__device__ float4 d_geoB[2][MAXN];  // c2, op*r, op*g, op*b
__device__ float4 d_bbox[2][MAXN];  // xmin, xmax, ymin, ymax

__global__ void prep_kernel(const float* __restrict__ lmu, const float* __restrict__ lch,
                            const float* __restrict__ lft, const float* __restrict__ lop,
                            const float* __restrict__ hmu, const float* __restrict__ hch,
                            const float* __restrict__ hft, const float* __restrict__ hop,
                            int nl, int nh)
{
    int i = blockIdx.x * blockDim.x + threadIdx.x;
    int slot, idx;
    const float *mu, *ch, *ft, *op;
    if (i < nl)            { slot = 0; idx = i;      mu = lmu; ch = lch; ft = lft; op = lop; }
    else if (i < nl + nh)  { slot = 1; idx = i - nl; mu = hmu; ch = hch; ft = hft; op = hop; }
    else return;

    float mx = tanhf(mu[idx * 2 + 0]);
    float my = tanhf(mu[idx * 2 + 1]);
    float x = (mx + 1.0f) * 0.5f * (float)IMG_W;
    float y = (my + 1.0f) * 0.5f * (float)IMG_H;

    // chol + bound [0.5, 0, 0.5]  (reference formulas verbatim)
    float l1 = ch[idx * 3 + 0] + 0.5f;
    float l2 = ch[idx * 3 + 1];
    float l3 = ch[idx * 3 + 2] + 0.5f;
    float sxx = l1 * l1;
    float sxy = l1 * l2;
    float syy = l2 * l2 + l3 * l3;
    float det = sxx * syy - sxy * sxy;
    float c0 =  syy / det;
    float c1 = -sxy / det;
    float c2 =  sxx / det;

    float o = op[idx];

    // Ellipse {sigma <= T} has axis-aligned extent sqrt(2*T*Sigma_xx/yy);
    // sxx, syy ARE the covariance diagonal. Small margin for safety.
    float rx = sqrtf(fmaxf(2.0f * SIGMA_T * sxx, 0.0f)) + 0.01f;
    float ry = sqrtf(fmaxf(2.0f * SIGMA_T * syy, 0.0f)) + 0.01f;

    d_geoA[slot][idx] = make_float4(x, y, c0, c1);
    d_geoB[slot][idx] = make_float4(c2, o * ft[idx * 3 + 0], o * ft[idx * 3 + 1], o * ft[idx * 3 + 2]);
    d_bbox[slot][idx] = make_float4(x - rx, x + rx, y - ry, y + ry);
}

__global__ __launch_bounds__(256, 2)
void render_kernel(const float* __restrict__ gfreq, const float* __restrict__ gwt,
                   int nl, int nh, float* __restrict__ out)
{
    __shared__ float4 sA[256];      // x, y, c0, c1
    __shared__ float4 sB[256];      // c2, r, g, b
    __shared__ float4 sF[256][2];   // fx0,fy0,fx1,fy1 | fx2,fy2,fx3,fy3
    __shared__ float4 sW[256];      // w0..w3
    __shared__ int    s_wc[8];

    const int tid = threadIdx.x;
    const int tx = blockIdx.x, ty = blockIdx.y;
    const int lx = tid & 15, ly = tid >> 4;

    const float px = (float)(tx * 16 + lx) + 0.5f;
    const float py = (float)(ty * 16 + ly) + 0.5f;
    const float txmin = (float)(tx * 16) + 0.5f, txmax = txmin + 15.0f;
    const float tymin = (float)(ty * 16) + 0.5f, tymax = tymin + 15.0f;

    const int warp = tid >> 5, lane = tid & 31;

    float ar = 0.0f, ag = 0.0f, ab = 0.0f;

    #pragma unroll
    for (int pass = 0; pass < 2; pass++) {
        const int n = pass ? nh : nl;
        for (int base = 0; base < n; base += 256) {
            const int i = base + tid;
            bool hit = false;
            if (i < n) {
                float4 bb = d_bbox[pass][i];
                hit = (bb.x <= txmax) & (bb.y >= txmin) & (bb.z <= tymax) & (bb.w >= tymin);
            }
            unsigned bal = __ballot_sync(0xffffffffu, hit);
            if (lane == 0) s_wc[warp] = __popc(bal);
            __syncthreads();
            int off = 0, total = 0;
            #pragma unroll
            for (int k = 0; k < 8; k++) {
                int c = s_wc[k];
                if (k < warp) off += c;
                total += c;
            }
            if (hit) {
                // order-preserving compaction -> deterministic accumulation order
                int pos = off + __popc(bal & ((1u << lane) - 1u));
                sA[pos] = d_geoA[pass][i];
                sB[pos] = d_geoB[pass][i];
                if (pass) {
                    const float2* f2 = (const float2*)gfreq;
                    float2 f0 = f2[i * GAB + 0];
                    float2 f1 = f2[i * GAB + 1];
                    float2 f2v = f2[i * GAB + 2];
                    float2 f3 = f2[i * GAB + 3];
                    sF[pos][0] = make_float4(f0.x, f0.y, f1.x, f1.y);
                    sF[pos][1] = make_float4(f2v.x, f2v.y, f3.x, f3.y);
                    sW[pos] = make_float4(gwt[i * GAB + 0], gwt[i * GAB + 1],
                                          gwt[i * GAB + 2], gwt[i * GAB + 3]);
                }
            }
            __syncthreads();

            if (!pass) {
                for (int j = 0; j < total; j++) {
                    float4 A = sA[j], B = sB[j];
                    float dx = px - A.x, dy = py - A.y;
                    float sig = 0.5f * A.z * dx * dx + A.w * dx * dy + 0.5f * B.x * dy * dy;
                    float w = __expf(-sig);
                    ar += w * B.y; ag += w * B.z; ab += w * B.w;
                }
            } else {
                for (int j = 0; j < total; j++) {
                    float4 A = sA[j], B = sB[j];
                    float dx = px - A.x, dy = py - A.y;
                    float sig = 0.5f * A.z * dx * dx + A.w * dx * dy + 0.5f * B.x * dy * dy;
                    float4 F0 = sF[j][0], F1 = sF[j][1], Wt = sW[j];
                    float mod = Wt.x * __cosf(F0.x * dx + F0.y * dy)
                              + Wt.y * __cosf(F0.z * dx + F0.w * dy)
                              + Wt.z * __cosf(F1.x * dx + F1.y * dy)
                              + Wt.w * __cosf(F1.z * dx + F1.w * dy);
                    float w = __expf(-sig) * mod;
                    ar += w * B.y; ag += w * B.z; ab += w * B.w;
                }
            }
            __syncthreads();
        }
    }

    const int pix = (ty * 16 + ly) * IMG_W + tx * 16 + lx;
    out[pix]                         = fminf(fmaxf(ar, 0.0f), 1.0f);
    out[IMG_H * IMG_W + pix]         = fminf(fmaxf(ag, 0.0f), 1.0f);
    out[2 * IMG_H * IMG_W + pix]     = fminf(fmaxf(ab, 0.0f), 1.0f);
}

extern "C" void kernel_launch(void* const* d_in, const int* in_sizes, int n_in,
                              void* d_out, int out_size)
{
    const float* low_mu    = (const float*)d_in[0];
    const float* high_mu   = (const float*)d_in[1];
    const float* low_chol  = (const float*)d_in[2];
    const float* high_chol = (const float*)d_in[3];
    const float* low_feat  = (const float*)d_in[4];
    const float* high_feat = (const float*)d_in[5];
    const float* low_opac  = (const float*)d_in[6];
    const float* high_opac = (const float*)d_in[7];
    const float* gfreq     = (const float*)d_in[8];
    const float* gwt       = (const float*)d_in[9];

    const int nl = in_sizes[6];   // low_opac is (nl, 1)
    const int nh = in_sizes[7];   // high_opac is (nh, 1)

    const int ntot = nl + nh;
    prep_kernel<<<(ntot + 255) / 256, 256>>>(low_mu, low_chol, low_feat, low_opac,
                                             high_mu, high_chol, high_feat, high_opac,
                                             nl, nh);

    dim3 grid(IMG_W / 16, IMG_H / 16);
    render_kernel<<<grid, 256>>>(gfreq, gwt, nl, nh, (float*)d_out);
}

// round 2
// speedup vs baseline: 1.1067x; 1.1067x over previous
#include <cuda_runtime.h>
#include <math.h>

#define IMG_W 256
#define IMG_H 256
#define GAB   4
#define MAXN  4096
#define SIGMA_T 30.0f
#define NTX 16
#define NTY 16
#define NTILES (NTX * NTY)
#define CAP 4096            // per-tile worst-case capacity (correctness guarantee)
#define MAXSORT 2048        // max entries a tile render can sort/process

// Static scratch — no allocation.
__device__ float4 d_geoA[2][MAXN];          // x, y, c0, c1
__device__ float4 d_geoB[2][MAXN];          // c2, op*r, op*g, op*b
__device__ int d_cnt[NTILES];
__device__ unsigned short d_list[NTILES][CAP];  // key = pass<<12 | idx

__global__ void zero_kernel()
{
    int t = threadIdx.x;
    if (t < NTILES) d_cnt[t] = 0;
}

__global__ void prep_bin_kernel(const float* __restrict__ lmu, const float* __restrict__ lch,
                                const float* __restrict__ lft, const float* __restrict__ lop,
                                const float* __restrict__ hmu, const float* __restrict__ hch,
                                const float* __restrict__ hft, const float* __restrict__ hop,
                                int nl, int nh)
{
    int i = blockIdx.x * blockDim.x + threadIdx.x;
    int slot, idx;
    const float *mu, *ch, *ft, *op;
    if (i < nl)            { slot = 0; idx = i;      mu = lmu; ch = lch; ft = lft; op = lop; }
    else if (i < nl + nh)  { slot = 1; idx = i - nl; mu = hmu; ch = hch; ft = hft; op = hop; }
    else return;

    float mx = tanhf(mu[idx * 2 + 0]);
    float my = tanhf(mu[idx * 2 + 1]);
    float x = (mx + 1.0f) * 0.5f * (float)IMG_W;
    float y = (my + 1.0f) * 0.5f * (float)IMG_H;

    float l1 = ch[idx * 3 + 0] + 0.5f;
    float l2 = ch[idx * 3 + 1];
    float l3 = ch[idx * 3 + 2] + 0.5f;
    float sxx = l1 * l1;
    float sxy = l1 * l2;
    float syy = l2 * l2 + l3 * l3;
    float det = sxx * syy - sxy * sxy;
    float c0 =  syy / det;
    float c1 = -sxy / det;
    float c2 =  sxx / det;

    float o = op[idx];

    float rx = sqrtf(fmaxf(2.0f * SIGMA_T * sxx, 0.0f)) + 0.01f;
    float ry = sqrtf(fmaxf(2.0f * SIGMA_T * syy, 0.0f)) + 0.01f;

    d_geoA[slot][idx] = make_float4(x, y, c0, c1);
    d_geoB[slot][idx] = make_float4(c2, o * ft[idx * 3 + 0], o * ft[idx * 3 + 1], o * ft[idx * 3 + 2]);

    // Tile range overlapped by bbox (tile t spans pixel centers [16t+0.5, 16t+15.5])
    float bxmin = x - rx, bxmax = x + rx;
    float bymin = y - ry, bymax = y + ry;
    int tx0 = max(0,      (int)ceilf ((bxmin - 15.5f) * (1.0f / 16.0f)));
    int tx1 = min(NTX - 1,(int)floorf((bxmax - 0.5f)  * (1.0f / 16.0f)));
    int ty0 = max(0,      (int)ceilf ((bymin - 15.5f) * (1.0f / 16.0f)));
    int ty1 = min(NTY - 1,(int)floorf((bymax - 0.5f)  * (1.0f / 16.0f)));

    unsigned short key = (unsigned short)((slot << 12) | idx);
    for (int ty = ty0; ty <= ty1; ty++)
        for (int tx = tx0; tx <= tx1; tx++) {
            int t = ty * NTX + tx;
            int s = atomicAdd(&d_cnt[t], 1);
            if (s < CAP) d_list[t][s] = key;
        }
}

__global__ __launch_bounds__(256, 2)
void render_kernel(const float* __restrict__ gfreq, const float* __restrict__ gwt,
                   float* __restrict__ out)
{
    __shared__ unsigned short sKey[MAXSORT];
    __shared__ unsigned short sSorted[MAXSORT];
    __shared__ float4 sA[128];
    __shared__ float4 sB[128];
    __shared__ float4 sF[128][2];
    __shared__ float4 sW[128];
    __shared__ unsigned short sK2[128];

    const int tid = threadIdx.x;
    const int tx = blockIdx.x, ty = blockIdx.y;
    const int tile = ty * NTX + tx;
    const int lx = tid & 15, ly = tid >> 4;

    const float px = (float)(tx * 16 + lx) + 0.5f;
    const float py = (float)(ty * 16 + ly) + 0.5f;

    int cnt = d_cnt[tile];
    cnt = min(cnt, CAP);
    cnt = min(cnt, MAXSORT);

    // Load keys to smem
    for (int e = tid; e < cnt; e += 256) sKey[e] = d_list[tile][e];
    __syncthreads();

    // Deterministic order: rank-sort by key (keys are unique).
    // Ascending => all low-pass splats (idx order) first, then high-pass.
    for (int e = tid; e < cnt; e += 256) {
        unsigned short k = sKey[e];
        int rank = 0;
        for (int j = 0; j < cnt; j++) rank += (sKey[j] < k);
        sSorted[rank] = k;
    }
    __syncthreads();

    float ar = 0.0f, ag = 0.0f, ab = 0.0f;

    for (int base = 0; base < cnt; base += 128) {
        const int m = min(128, cnt - base);
        if (tid < m) {
            unsigned short k = sSorted[base + tid];
            int pass = k >> 12;
            int idx  = k & 0xFFF;
            sK2[tid] = k;
            sA[tid] = d_geoA[pass][idx];
            sB[tid] = d_geoB[pass][idx];
            if (pass) {
                const float2* f2 = (const float2*)gfreq;
                float2 f0 = f2[idx * GAB + 0];
                float2 f1 = f2[idx * GAB + 1];
                float2 f2v = f2[idx * GAB + 2];
                float2 f3 = f2[idx * GAB + 3];
                sF[tid][0] = make_float4(f0.x, f0.y, f1.x, f1.y);
                sF[tid][1] = make_float4(f2v.x, f2v.y, f3.x, f3.y);
                sW[tid] = make_float4(gwt[idx * GAB + 0], gwt[idx * GAB + 1],
                                      gwt[idx * GAB + 2], gwt[idx * GAB + 3]);
            }
        }
        __syncthreads();

        for (int j = 0; j < m; j++) {
            float4 A = sA[j], B = sB[j];
            float dx = px - A.x, dy = py - A.y;
            float sig = 0.5f * A.z * dx * dx + A.w * dx * dy + 0.5f * B.x * dy * dy;
            float w = __expf(-sig);
            if (sK2[j] >> 12) {
                float4 F0 = sF[j][0], F1 = sF[j][1], Wt = sW[j];
                float mod = Wt.x * __cosf(F0.x * dx + F0.y * dy)
                          + Wt.y * __cosf(F0.z * dx + F0.w * dy)
                          + Wt.z * __cosf(F1.x * dx + F1.y * dy)
                          + Wt.w * __cosf(F1.z * dx + F1.w * dy);
                w *= mod;
            }
            ar += w * B.y; ag += w * B.z; ab += w * B.w;
        }
        __syncthreads();
    }

    const int pix = (ty * 16 + ly) * IMG_W + tx * 16 + lx;
    out[pix]                     = fminf(fmaxf(ar, 0.0f), 1.0f);
    out[IMG_H * IMG_W + pix]     = fminf(fmaxf(ag, 0.0f), 1.0f);
    out[2 * IMG_H * IMG_W + pix] = fminf(fmaxf(ab, 0.0f), 1.0f);
}

extern "C" void kernel_launch(void* const* d_in, const int* in_sizes, int n_in,
                              void* d_out, int out_size)
{
    const float* low_mu    = (const float*)d_in[0];
    const float* high_mu   = (const float*)d_in[1];
    const float* low_chol  = (const float*)d_in[2];
    const float* high_chol = (const float*)d_in[3];
    const float* low_feat  = (const float*)d_in[4];
    const float* high_feat = (const float*)d_in[5];
    const float* low_opac  = (const float*)d_in[6];
    const float* high_opac = (const float*)d_in[7];
    const float* gfreq     = (const float*)d_in[8];
    const float* gwt       = (const float*)d_in[9];

    const int nl = in_sizes[6];
    const int nh = in_sizes[7];

    zero_kernel<<<1, 256>>>();

    const int ntot = nl + nh;
    prep_bin_kernel<<<(ntot + 255) / 256, 256>>>(low_mu, low_chol, low_feat, low_opac,
                                                 high_mu, high_chol, high_feat, high_opac,
                                                 nl, nh);

    dim3 grid(NTX, NTY);
    render_kernel<<<grid, 256>>>(gfreq, gwt, (float*)d_out);
}